// round 7
// baseline (speedup 1.0000x reference)
#include <cuda_runtime.h>
#include <math.h>
#include <stdint.h>

// Problem constants
#define B 8
#define S 1024
#define D 1024
#define H 16
#define HD 64
#define MROWS (B * S)   // 8192

// ---------------- scratch (no runtime allocation allowed) ----------------
__device__ float g_q[MROWS * D];
__device__ float g_k[MROWS * D];
__device__ float g_v[MROWS * D];
__device__ float g_ao[MROWS * D];
__device__ float g_x[MROWS * D];        // tf32-rounded, col-pair-interleaved x
__device__ float g_wq[D * D];           // tf32-rounded, interleaved weights
__device__ float g_wk[D * D];
__device__ float g_wv[D * D];
__device__ float g_wo[D * D];

// ===================== tf32 mma helpers ===================================
__device__ __forceinline__ uint32_t f2tf32(float v) {
    uint32_t u;
    asm("cvt.rna.tf32.f32 %0, %1;" : "=r"(u) : "f"(v));
    return u;
}

__device__ __forceinline__ void mma_tf32(float* c, const uint32_t* a,
                                         const uint32_t* b) {
    asm volatile(
        "mma.sync.aligned.m16n8k8.row.col.f32.tf32.tf32.f32 "
        "{%0,%1,%2,%3}, {%4,%5,%6,%7}, {%8,%9}, {%0,%1,%2,%3};"
        : "+f"(c[0]), "+f"(c[1]), "+f"(c[2]), "+f"(c[3])
        : "r"(a[0]), "r"(a[1]), "r"(a[2]), "r"(a[3]), "r"(b[0]), "r"(b[1]));
}

__device__ __forceinline__ uint32_t smem_u32(const void* p) {
    uint32_t a;
    asm("{ .reg .u64 t; cvta.to.shared.u64 t, %1; cvt.u32.u64 %0, t; }"
        : "=r"(a) : "l"(p));
    return a;
}

__device__ __forceinline__ void cp_async16(uint32_t dst, const void* src) {
    asm volatile("cp.async.cg.shared.global [%0], [%1], 16;"
                 :: "r"(dst), "l"(src));
}
#define CP_COMMIT() asm volatile("cp.async.commit_group;" ::: "memory")
#define CP_WAIT(n)  asm volatile("cp.async.wait_group %0;" :: "n"(n) : "memory")

// ====== prep: round to tf32 + interleave column pairs within 8-groups =====
// source col j (0..7 of each group) -> position (j&3)*2 + (j>>2):
// [c0 c4 c1 c5 c2 c6 c3 c7]  => frag pair (c, c+4) adjacent.
__global__ void round_perm_kernel(const float* __restrict__ src,
                                  float* __restrict__ dst, int n8) {
    int i = blockIdx.x * blockDim.x + threadIdx.x;
    if (i < n8) {
        const float4 lo = reinterpret_cast<const float4*>(src)[i * 2];
        const float4 hi = reinterpret_cast<const float4*>(src)[i * 2 + 1];
        float4 o0 = make_float4(__uint_as_float(f2tf32(lo.x)),
                                __uint_as_float(f2tf32(hi.x)),
                                __uint_as_float(f2tf32(lo.y)),
                                __uint_as_float(f2tf32(hi.y)));
        float4 o1 = make_float4(__uint_as_float(f2tf32(lo.z)),
                                __uint_as_float(f2tf32(hi.z)),
                                __uint_as_float(f2tf32(lo.w)),
                                __uint_as_float(f2tf32(hi.w)));
        reinterpret_cast<float4*>(dst)[i * 2] = o0;
        reinterpret_cast<float4*>(dst)[i * 2 + 1] = o1;
    }
}

// ===================== tf32 mma.sync GEMM: C = A * W^T ====================
// Inputs pre-rounded + pair-interleaved. Pitch 40 (mod 32 = 8) makes the
// float2 fragment LDS conflict-free (banks 8r+2c distinct per half-warp).
#define GP 40
#define GSTAGE (128 * GP)                // floats per matrix per stage
#define GEMM_SMEM (2 * 2 * GSTAGE * 4)   // 81920 B

template <bool ROUND_OUT>
__global__ void __launch_bounds__(256, 2)
gemm_tc_kernel(const float* __restrict__ A, const float* __restrict__ W,
               float* __restrict__ C) {
    extern __shared__ float sm[];
    const int tid = threadIdx.x;
    const int lane = tid & 31;
    const int wid = tid >> 5;
    const int wm = wid & 3;
    const int wn = wid >> 2;
    const int c = lane & 3;
    const int r = lane >> 2;
    const int bn = blockIdx.x * 128;
    const int bm = blockIdx.y * 128;

    float acc[2][8][4];
#pragma unroll
    for (int m = 0; m < 2; m++)
#pragma unroll
        for (int n = 0; n < 8; n++)
#pragma unroll
            for (int i = 0; i < 4; i++) acc[m][n][i] = 0.0f;

    const int gr = tid >> 3;          // 0..31
    const int gc = (tid & 7) * 4;     // 0..28

    auto stage = [&](int k0, float* sA, float* sB) {
#pragma unroll
        for (int it = 0; it < 4; it++) {
            int row = it * 32 + gr;
            cp_async16(smem_u32(sA + row * GP + gc),
                       A + (size_t)(bm + row) * 1024 + k0 + gc);
            cp_async16(smem_u32(sB + row * GP + gc),
                       W + (size_t)(bn + row) * 1024 + k0 + gc);
        }
        CP_COMMIT();
    };

    auto compute = [&](const float* sA, const float* sB) {
#pragma unroll
        for (int ks = 0; ks < 4; ks++) {
            const int co = ks * 8 + 2 * c;
            uint32_t af[2][4];
#pragma unroll
            for (int m = 0; m < 2; m++) {
                const int row = wm * 32 + m * 16 + r;
                const float2 x0 =
                    *reinterpret_cast<const float2*>(sA + row * GP + co);
                const float2 x1 =
                    *reinterpret_cast<const float2*>(sA + (row + 8) * GP + co);
                af[m][0] = __float_as_uint(x0.x);
                af[m][1] = __float_as_uint(x1.x);
                af[m][2] = __float_as_uint(x0.y);
                af[m][3] = __float_as_uint(x1.y);
            }
            uint32_t bf[8][2];
#pragma unroll
            for (int n = 0; n < 8; n++) {
                const float2 y = *reinterpret_cast<const float2*>(
                    sB + (wn * 64 + n * 8 + r) * GP + co);
                bf[n][0] = __float_as_uint(y.x);
                bf[n][1] = __float_as_uint(y.y);
            }
#pragma unroll
            for (int m = 0; m < 2; m++)
#pragma unroll
                for (int n = 0; n < 8; n++) mma_tf32(acc[m][n], af[m], bf[n]);
        }
    };

    float* buf0 = sm;                     // [A | B] stage 0
    float* buf1 = sm + 2 * GSTAGE;        // [A | B] stage 1

    stage(0, buf0, buf0 + GSTAGE);

    for (int t = 0; t < 32; t++) {
        float* cur = (t & 1) ? buf1 : buf0;
        float* nxt = (t & 1) ? buf0 : buf1;
        __syncthreads();   // all warps done computing on nxt (iter t-1)
        if (t < 31) {
            stage((t + 1) * 32, nxt, nxt + GSTAGE);
            CP_WAIT(1);    // group for cur complete
        } else {
            CP_WAIT(0);
        }
        __syncthreads();   // cur visible to all warps
        compute(cur, cur + GSTAGE);
    }

    const int qr = lane >> 2;
    const int qc = (lane & 3) * 2;
#pragma unroll
    for (int m = 0; m < 2; m++) {
        const int row0 = bm + wm * 32 + m * 16 + qr;
#pragma unroll
        for (int n = 0; n < 8; n++) {
            const int col = bn + wn * 64 + n * 8 + qc;
            float o0 = acc[m][n][0], o1 = acc[m][n][1];
            float o2 = acc[m][n][2], o3 = acc[m][n][3];
            if (ROUND_OUT) {
                o0 = __uint_as_float(f2tf32(o0));
                o1 = __uint_as_float(f2tf32(o1));
                o2 = __uint_as_float(f2tf32(o2));
                o3 = __uint_as_float(f2tf32(o3));
            }
            *reinterpret_cast<float2*>(C + (size_t)row0 * 1024 + col) =
                make_float2(o0, o1);
            *reinterpret_cast<float2*>(C + (size_t)(row0 + 8) * 1024 + col) =
                make_float2(o2, o3);
        }
    }
}

// ============ tf32 tensor-core flash attention (cp.async 2-stage) =========
// q/k/v natural layout (tf32 values). Epilogue writes ao PERMUTED for the
// final GEMM (rounded to tf32).
#define KVPITCH 68
#define SSTAGE (2 * 64 * KVPITCH)          // floats per stage (K+V)
#define ATTN_SMEM (2 * SSTAGE * 4)         // 69632 B

__global__ void __launch_bounds__(256, 1)
attn_tc_kernel(const float* __restrict__ Q, const float* __restrict__ K,
               const float* __restrict__ V, float* __restrict__ O) {
    extern __shared__ float sm[];

    const int tid = threadIdx.x;
    const int lane = tid & 31;
    const int wid = tid >> 5;
    const int c = lane & 3;
    const int r = lane >> 2;
    const int b = blockIdx.z;
    const int h = blockIdx.y;
    const int q0 = blockIdx.x * 128;
    const int wrow = wid * 16;

    const float* Qb = Q + ((size_t)(b * S + q0) * D) + h * HD;
    const float* Kb = K + ((size_t)b * S) * D + h * HD;
    const float* Vb = V + ((size_t)b * S) * D + h * HD;

    auto load_kv = [&](int kt0, float* base) {
        float* Kst = base;
        float* Vst = base + 64 * KVPITCH;
#pragma unroll
        for (int i = 0; i < 4; i++) {
            const int idx = tid + i * 256;
            const int row = idx >> 4, c4 = (idx & 15) * 4;
            cp_async16(smem_u32(Kst + row * KVPITCH + c4),
                       Kb + (size_t)(kt0 + row) * D + c4);
            cp_async16(smem_u32(Vst + row * KVPITCH + c4),
                       Vb + (size_t)(kt0 + row) * D + c4);
        }
        CP_COMMIT();
    };

    // Q fragments (values already tf32; *0.125 is exact)
    uint32_t qf[8][4];
#pragma unroll
    for (int ks = 0; ks < 8; ks++) {
        const int row0 = wrow + r, row1 = row0 + 8, col = ks * 8 + c;
        qf[ks][0] = __float_as_uint(Qb[(size_t)row0 * D + col] * 0.125f);
        qf[ks][1] = __float_as_uint(Qb[(size_t)row1 * D + col] * 0.125f);
        qf[ks][2] = __float_as_uint(Qb[(size_t)row0 * D + col + 4] * 0.125f);
        qf[ks][3] = __float_as_uint(Qb[(size_t)row1 * D + col + 4] * 0.125f);
    }

    float oacc[8][4];
#pragma unroll
    for (int n = 0; n < 8; n++)
#pragma unroll
        for (int i = 0; i < 4; i++) oacc[n][i] = 0.0f;
    float m0 = -1e30f, m1 = -1e30f, l0 = 0.0f, l1 = 0.0f;

    load_kv(0, sm);

    for (int t = 0; t < 16; t++) {
        float* cur = sm + (t & 1) * SSTAGE;
        float* nxt = sm + ((t + 1) & 1) * SSTAGE;
        __syncthreads();   // all warps done with nxt (used at t-1)
        if (t < 15) {
            load_kv((t + 1) * 64, nxt);
            CP_WAIT(1);
        } else {
            CP_WAIT(0);
        }
        __syncthreads();   // cur visible
        const float* Ks = cur;
        const float* Vs = cur + 64 * KVPITCH;

        // S = Q . K^T
        float sacc[8][4];
#pragma unroll
        for (int n = 0; n < 8; n++)
#pragma unroll
            for (int i = 0; i < 4; i++) sacc[n][i] = 0.0f;

#pragma unroll
        for (int ks = 0; ks < 8; ks++) {
#pragma unroll
            for (int nt = 0; nt < 8; nt++) {
                uint32_t bf[2];
                const float* kp = Ks + (nt * 8 + r) * KVPITCH + ks * 8 + c;
                bf[0] = __float_as_uint(kp[0]);
                bf[1] = __float_as_uint(kp[4]);
                mma_tf32(sacc[nt], qf[ks], bf);
            }
        }

        // online softmax on C-fragments
        float rmax0 = -1e30f, rmax1 = -1e30f;
#pragma unroll
        for (int nt = 0; nt < 8; nt++) {
            rmax0 = fmaxf(rmax0, fmaxf(sacc[nt][0], sacc[nt][1]));
            rmax1 = fmaxf(rmax1, fmaxf(sacc[nt][2], sacc[nt][3]));
        }
#pragma unroll
        for (int off = 1; off <= 2; off <<= 1) {
            rmax0 = fmaxf(rmax0, __shfl_xor_sync(0xffffffffu, rmax0, off));
            rmax1 = fmaxf(rmax1, __shfl_xor_sync(0xffffffffu, rmax1, off));
        }
        const float mn0 = fmaxf(m0, rmax0);
        const float mn1 = fmaxf(m1, rmax1);
        const float alpha0 = __expf(m0 - mn0);
        const float alpha1 = __expf(m1 - mn1);
        float rs0 = 0.0f, rs1 = 0.0f;
#pragma unroll
        for (int nt = 0; nt < 8; nt++) {
            sacc[nt][0] = __expf(sacc[nt][0] - mn0);
            sacc[nt][1] = __expf(sacc[nt][1] - mn0);
            sacc[nt][2] = __expf(sacc[nt][2] - mn1);
            sacc[nt][3] = __expf(sacc[nt][3] - mn1);
            rs0 += sacc[nt][0] + sacc[nt][1];
            rs1 += sacc[nt][2] + sacc[nt][3];
        }
#pragma unroll
        for (int off = 1; off <= 2; off <<= 1) {
            rs0 += __shfl_xor_sync(0xffffffffu, rs0, off);
            rs1 += __shfl_xor_sync(0xffffffffu, rs1, off);
        }
        l0 = l0 * alpha0 + rs0;
        l1 = l1 * alpha1 + rs1;
        m0 = mn0;
        m1 = mn1;
#pragma unroll
        for (int nt = 0; nt < 8; nt++) {
            oacc[nt][0] *= alpha0;
            oacc[nt][1] *= alpha0;
            oacc[nt][2] *= alpha1;
            oacc[nt][3] *= alpha1;
        }

        // P (C-frag) -> A-frag via intra-quad shuffles, then O += P.V
        const int srcA = (lane & ~3) | (c >> 1);
        const int srcB = srcA + 2;
#pragma unroll
        for (int kt = 0; kt < 8; kt++) {
            const float v00 = __shfl_sync(0xffffffffu, sacc[kt][0], srcA);
            const float v01 = __shfl_sync(0xffffffffu, sacc[kt][1], srcA);
            const float v20 = __shfl_sync(0xffffffffu, sacc[kt][2], srcA);
            const float v21 = __shfl_sync(0xffffffffu, sacc[kt][3], srcA);
            const float w00 = __shfl_sync(0xffffffffu, sacc[kt][0], srcB);
            const float w01 = __shfl_sync(0xffffffffu, sacc[kt][1], srcB);
            const float w20 = __shfl_sync(0xffffffffu, sacc[kt][2], srcB);
            const float w21 = __shfl_sync(0xffffffffu, sacc[kt][3], srcB);
            uint32_t af[4];
            af[0] = f2tf32((c & 1) ? v01 : v00);
            af[1] = f2tf32((c & 1) ? v21 : v20);
            af[2] = f2tf32((c & 1) ? w01 : w00);
            af[3] = f2tf32((c & 1) ? w21 : w20);
#pragma unroll
            for (int nt = 0; nt < 8; nt++) {
                uint32_t bf[2];
                const float* vp = Vs + (kt * 8 + c) * KVPITCH + nt * 8 + r;
                bf[0] = __float_as_uint(vp[0]);
                bf[1] = __float_as_uint(vp[4 * KVPITCH]);
                mma_tf32(oacc[nt], af, bf);
            }
        }
    }

    // epilogue: divide by l, round to tf32, write PERMUTED columns
    // source col j -> position (j&3)*2 + (j>>2) within each 8-col group.
    const float inv0 = 1.0f / l0;
    const float inv1 = 1.0f / l1;
    const int j0 = 2 * c, j1 = 2 * c + 1;
    const int p0 = (j0 & 3) * 2 + (j0 >> 2);
    const int p1 = (j1 & 3) * 2 + (j1 >> 2);
    float* Ob = O + ((size_t)(b * S + q0 + wrow) * D) + h * HD;
#pragma unroll
    for (int nt = 0; nt < 8; nt++) {
        Ob[(size_t)r * D + nt * 8 + p0] =
            __uint_as_float(f2tf32(oacc[nt][0] * inv0));
        Ob[(size_t)r * D + nt * 8 + p1] =
            __uint_as_float(f2tf32(oacc[nt][1] * inv0));
        Ob[(size_t)(r + 8) * D + nt * 8 + p0] =
            __uint_as_float(f2tf32(oacc[nt][2] * inv1));
        Ob[(size_t)(r + 8) * D + nt * 8 + p1] =
            __uint_as_float(f2tf32(oacc[nt][3] * inv1));
    }
}

// ---------------- launch ----------------
extern "C" void kernel_launch(void* const* d_in, const int* in_sizes, int n_in,
                              void* d_out, int out_size) {
    const float* x  = (const float*)d_in[0];
    const float* wq = (const float*)d_in[1];
    const float* wk = (const float*)d_in[2];
    const float* wv = (const float*)d_in[3];
    const float* wo = (const float*)d_in[4];
    float* out = (float*)d_out;

    float* q;   cudaGetSymbolAddress((void**)&q,   g_q);
    float* k;   cudaGetSymbolAddress((void**)&k,   g_k);
    float* v;   cudaGetSymbolAddress((void**)&v,   g_v);
    float* ao;  cudaGetSymbolAddress((void**)&ao,  g_ao);
    float* xr;  cudaGetSymbolAddress((void**)&xr,  g_x);
    float* wqr; cudaGetSymbolAddress((void**)&wqr, g_wq);
    float* wkr; cudaGetSymbolAddress((void**)&wkr, g_wk);
    float* wvr; cudaGetSymbolAddress((void**)&wvr, g_wv);
    float* wor; cudaGetSymbolAddress((void**)&wor, g_wo);

    cudaFuncSetAttribute(gemm_tc_kernel<true>,
                         cudaFuncAttributeMaxDynamicSharedMemorySize, GEMM_SMEM);
    cudaFuncSetAttribute(gemm_tc_kernel<false>,
                         cudaFuncAttributeMaxDynamicSharedMemorySize, GEMM_SMEM);
    cudaFuncSetAttribute(attn_tc_kernel,
                         cudaFuncAttributeMaxDynamicSharedMemorySize, ATTN_SMEM);

    // prep: round + pair-interleave x and weights
    const int nx8 = MROWS * D / 8;         // 1048576
    const int nw8 = D * D / 8;             // 131072
    round_perm_kernel<<<(nx8 + 255) / 256, 256>>>(x, xr, nx8);
    round_perm_kernel<<<(nw8 + 255) / 256, 256>>>(wq, wqr, nw8);
    round_perm_kernel<<<(nw8 + 255) / 256, 256>>>(wk, wkr, nw8);
    round_perm_kernel<<<(nw8 + 255) / 256, 256>>>(wv, wvr, nw8);
    round_perm_kernel<<<(nw8 + 255) / 256, 256>>>(wo, wor, nw8);

    dim3 gemm_grid(D / 128, MROWS / 128);   // (8, 64)
    gemm_tc_kernel<true><<<gemm_grid, 256, GEMM_SMEM>>>(xr, wqr, q);
    gemm_tc_kernel<true><<<gemm_grid, 256, GEMM_SMEM>>>(xr, wkr, k);
    gemm_tc_kernel<true><<<gemm_grid, 256, GEMM_SMEM>>>(xr, wvr, v);

    dim3 attn_grid(S / 128, H, B);          // (8, 16, 8)
    attn_tc_kernel<<<attn_grid, 256, ATTN_SMEM>>>(q, k, v, ao);

    gemm_tc_kernel<false><<<gemm_grid, 256, GEMM_SMEM>>>(ao, wor, out);
}

// round 8
// speedup vs baseline: 1.0492x; 1.0492x over previous
#include <cuda_runtime.h>
#include <math.h>
#include <stdint.h>

// Problem constants
#define B 8
#define S 1024
#define D 1024
#define H 16
#define HD 64
#define MROWS (B * S)   // 8192

// ---------------- scratch (no runtime allocation allowed) ----------------
__device__ float g_q[MROWS * D];
__device__ float g_k[MROWS * D];
__device__ float g_v[MROWS * D];
__device__ float g_ao[MROWS * D];
__device__ float g_x[MROWS * D];        // tf32-rounded x
__device__ float g_wq[D * D];           // tf32-rounded weights
__device__ float g_wk[D * D];
__device__ float g_wv[D * D];
__device__ float g_wo[D * D];

// ===================== tf32 mma helpers ===================================
__device__ __forceinline__ uint32_t f2tf32(float v) {
    uint32_t u;
    asm("cvt.rna.tf32.f32 %0, %1;" : "=r"(u) : "f"(v));
    return u;
}

__device__ __forceinline__ void mma_tf32(float* c, const uint32_t* a,
                                         const uint32_t* b) {
    asm volatile(
        "mma.sync.aligned.m16n8k8.row.col.f32.tf32.tf32.f32 "
        "{%0,%1,%2,%3}, {%4,%5,%6,%7}, {%8,%9}, {%0,%1,%2,%3};"
        : "+f"(c[0]), "+f"(c[1]), "+f"(c[2]), "+f"(c[3])
        : "r"(a[0]), "r"(a[1]), "r"(a[2]), "r"(a[3]), "r"(b[0]), "r"(b[1]));
}

__device__ __forceinline__ uint32_t smem_u32(const void* p) {
    uint32_t a;
    asm("{ .reg .u64 t; cvta.to.shared.u64 t, %1; cvt.u32.u64 %0, t; }"
        : "=r"(a) : "l"(p));
    return a;
}

__device__ __forceinline__ void cp_async16(uint32_t dst, const void* src) {
    asm volatile("cp.async.cg.shared.global [%0], [%1], 16;"
                 :: "r"(dst), "l"(src));
}
#define CP_COMMIT() asm volatile("cp.async.commit_group;" ::: "memory")
#define CP_WAIT(n)  asm volatile("cp.async.wait_group %0;" :: "n"(n) : "memory")

// ================ prep: round arrays to tf32 in gmem ======================
__global__ void round_tf32_kernel(const float* __restrict__ src,
                                  float* __restrict__ dst, int n4) {
    int i = blockIdx.x * blockDim.x + threadIdx.x;
    if (i < n4) {
        float4 v = reinterpret_cast<const float4*>(src)[i];
        reinterpret_cast<float4*>(dst)[i] =
            make_float4(__uint_as_float(f2tf32(v.x)),
                        __uint_as_float(f2tf32(v.y)),
                        __uint_as_float(f2tf32(v.z)),
                        __uint_as_float(f2tf32(v.w)));
    }
}

// ===================== tf32 mma.sync GEMM: C = A * W^T ====================
// (round-6 configuration: natural layout, pitch 36, cp.async staging)
#define GP 36
#define GSTAGE (128 * GP)                // floats per matrix per stage
#define GEMM_SMEM (2 * 2 * GSTAGE * 4)   // 73728 B

template <bool ROUND_OUT>
__global__ void __launch_bounds__(256, 2)
gemm_tc_kernel(const float* __restrict__ A, const float* __restrict__ W,
               float* __restrict__ C) {
    extern __shared__ float sm[];
    const int tid = threadIdx.x;
    const int lane = tid & 31;
    const int wid = tid >> 5;
    const int wm = wid & 3;
    const int wn = wid >> 2;
    const int c = lane & 3;
    const int r = lane >> 2;
    const int bn = blockIdx.x * 128;
    const int bm = blockIdx.y * 128;

    float acc[2][8][4];
#pragma unroll
    for (int m = 0; m < 2; m++)
#pragma unroll
        for (int n = 0; n < 8; n++)
#pragma unroll
            for (int i = 0; i < 4; i++) acc[m][n][i] = 0.0f;

    const int gr = tid >> 3;          // 0..31
    const int gc = (tid & 7) * 4;     // 0..28

    auto stage = [&](int k0, float* sA, float* sB) {
#pragma unroll
        for (int it = 0; it < 4; it++) {
            int row = it * 32 + gr;
            cp_async16(smem_u32(sA + row * GP + gc),
                       A + (size_t)(bm + row) * 1024 + k0 + gc);
            cp_async16(smem_u32(sB + row * GP + gc),
                       W + (size_t)(bn + row) * 1024 + k0 + gc);
        }
        CP_COMMIT();
    };

    auto compute = [&](const float* sA, const float* sB) {
#pragma unroll
        for (int ks = 0; ks < 4; ks++) {
            uint32_t af[2][4];
#pragma unroll
            for (int m = 0; m < 2; m++) {
                const float* ap = sA + (wm * 32 + m * 16 + r) * GP + ks * 8 + c;
                af[m][0] = __float_as_uint(ap[0]);
                af[m][1] = __float_as_uint(ap[8 * GP]);
                af[m][2] = __float_as_uint(ap[4]);
                af[m][3] = __float_as_uint(ap[8 * GP + 4]);
            }
            uint32_t bf[8][2];
#pragma unroll
            for (int n = 0; n < 8; n++) {
                const float* bp = sB + (wn * 64 + n * 8 + r) * GP + ks * 8 + c;
                bf[n][0] = __float_as_uint(bp[0]);
                bf[n][1] = __float_as_uint(bp[4]);
            }
#pragma unroll
            for (int m = 0; m < 2; m++)
#pragma unroll
                for (int n = 0; n < 8; n++) mma_tf32(acc[m][n], af[m], bf[n]);
        }
    };

    float* buf0 = sm;                     // [A | B] stage 0
    float* buf1 = sm + 2 * GSTAGE;        // [A | B] stage 1

    stage(0, buf0, buf0 + GSTAGE);

    for (int t = 0; t < 32; t++) {
        float* cur = (t & 1) ? buf1 : buf0;
        float* nxt = (t & 1) ? buf0 : buf1;
        __syncthreads();   // all warps done computing on nxt (iter t-1)
        if (t < 31) {
            stage((t + 1) * 32, nxt, nxt + GSTAGE);
            CP_WAIT(1);    // group for cur complete
        } else {
            CP_WAIT(0);
        }
        __syncthreads();   // cur visible to all warps
        compute(cur, cur + GSTAGE);
    }

    const int qr = lane >> 2;
    const int qc = (lane & 3) * 2;
#pragma unroll
    for (int m = 0; m < 2; m++) {
        const int row0 = bm + wm * 32 + m * 16 + qr;
#pragma unroll
        for (int n = 0; n < 8; n++) {
            const int col = bn + wn * 64 + n * 8 + qc;
            float o0 = acc[m][n][0], o1 = acc[m][n][1];
            float o2 = acc[m][n][2], o3 = acc[m][n][3];
            if (ROUND_OUT) {
                o0 = __uint_as_float(f2tf32(o0));
                o1 = __uint_as_float(f2tf32(o1));
                o2 = __uint_as_float(f2tf32(o2));
                o3 = __uint_as_float(f2tf32(o3));
            }
            *reinterpret_cast<float2*>(C + (size_t)row0 * 1024 + col) =
                make_float2(o0, o1);
            *reinterpret_cast<float2*>(C + (size_t)(row0 + 8) * 1024 + col) =
                make_float2(o2, o3);
        }
    }
}

// ============ tf32 tensor-core flash attention ============================
// 128 threads (4 warps), 64 q-rows per CTA, 3 CTAs/SM (12 warps/SM).
// KV tiles (64 keys) double-buffered via cp.async, natural layout pitch 68.
#define KVPITCH 68
#define SSTAGE (2 * 64 * KVPITCH)          // floats per stage (K+V)
#define ATTN_SMEM (2 * SSTAGE * 4)         // 69632 B

__global__ void __launch_bounds__(128, 3)
attn_tc_kernel(const float* __restrict__ Q, const float* __restrict__ K,
               const float* __restrict__ V, float* __restrict__ O) {
    extern __shared__ float sm[];

    const int tid = threadIdx.x;
    const int lane = tid & 31;
    const int wid = tid >> 5;          // 0..3
    const int c = lane & 3;
    const int r = lane >> 2;
    const int b = blockIdx.z;
    const int h = blockIdx.y;
    const int q0 = blockIdx.x * 64;
    const int wrow = wid * 16;

    const float* Qb = Q + ((size_t)(b * S + q0) * D) + h * HD;
    const float* Kb = K + ((size_t)b * S) * D + h * HD;
    const float* Vb = V + ((size_t)b * S) * D + h * HD;

    auto load_kv = [&](int kt0, float* base) {
        float* Kst = base;
        float* Vst = base + 64 * KVPITCH;
#pragma unroll
        for (int i = 0; i < 8; i++) {
            const int idx = tid + i * 128;
            const int row = idx >> 4, c4 = (idx & 15) * 4;
            cp_async16(smem_u32(Kst + row * KVPITCH + c4),
                       Kb + (size_t)(kt0 + row) * D + c4);
            cp_async16(smem_u32(Vst + row * KVPITCH + c4),
                       Vb + (size_t)(kt0 + row) * D + c4);
        }
        CP_COMMIT();
    };

    // Q fragments (values already tf32; *0.125 is exact)
    uint32_t qf[8][4];
#pragma unroll
    for (int ks = 0; ks < 8; ks++) {
        const int row0 = wrow + r, row1 = row0 + 8, col = ks * 8 + c;
        qf[ks][0] = __float_as_uint(Qb[(size_t)row0 * D + col] * 0.125f);
        qf[ks][1] = __float_as_uint(Qb[(size_t)row1 * D + col] * 0.125f);
        qf[ks][2] = __float_as_uint(Qb[(size_t)row0 * D + col + 4] * 0.125f);
        qf[ks][3] = __float_as_uint(Qb[(size_t)row1 * D + col + 4] * 0.125f);
    }

    float oacc[8][4];
#pragma unroll
    for (int n = 0; n < 8; n++)
#pragma unroll
        for (int i = 0; i < 4; i++) oacc[n][i] = 0.0f;
    float m0 = -1e30f, m1 = -1e30f, l0 = 0.0f, l1 = 0.0f;

    load_kv(0, sm);

    for (int t = 0; t < 16; t++) {
        float* cur = sm + (t & 1) * SSTAGE;
        float* nxt = sm + ((t + 1) & 1) * SSTAGE;
        __syncthreads();   // all warps done with nxt (used at t-1)
        if (t < 15) {
            load_kv((t + 1) * 64, nxt);
            CP_WAIT(1);
        } else {
            CP_WAIT(0);
        }
        __syncthreads();   // cur visible
        const float* Ks = cur;
        const float* Vs = cur + 64 * KVPITCH;

        // S = Q . K^T
        float sacc[8][4];
#pragma unroll
        for (int n = 0; n < 8; n++)
#pragma unroll
            for (int i = 0; i < 4; i++) sacc[n][i] = 0.0f;

#pragma unroll
        for (int ks = 0; ks < 8; ks++) {
#pragma unroll
            for (int nt = 0; nt < 8; nt++) {
                uint32_t bf[2];
                const float* kp = Ks + (nt * 8 + r) * KVPITCH + ks * 8 + c;
                bf[0] = __float_as_uint(kp[0]);
                bf[1] = __float_as_uint(kp[4]);
                mma_tf32(sacc[nt], qf[ks], bf);
            }
        }

        // online softmax on C-fragments
        float rmax0 = -1e30f, rmax1 = -1e30f;
#pragma unroll
        for (int nt = 0; nt < 8; nt++) {
            rmax0 = fmaxf(rmax0, fmaxf(sacc[nt][0], sacc[nt][1]));
            rmax1 = fmaxf(rmax1, fmaxf(sacc[nt][2], sacc[nt][3]));
        }
#pragma unroll
        for (int off = 1; off <= 2; off <<= 1) {
            rmax0 = fmaxf(rmax0, __shfl_xor_sync(0xffffffffu, rmax0, off));
            rmax1 = fmaxf(rmax1, __shfl_xor_sync(0xffffffffu, rmax1, off));
        }
        const float mn0 = fmaxf(m0, rmax0);
        const float mn1 = fmaxf(m1, rmax1);
        const float alpha0 = __expf(m0 - mn0);
        const float alpha1 = __expf(m1 - mn1);
        float rs0 = 0.0f, rs1 = 0.0f;
#pragma unroll
        for (int nt = 0; nt < 8; nt++) {
            sacc[nt][0] = __expf(sacc[nt][0] - mn0);
            sacc[nt][1] = __expf(sacc[nt][1] - mn0);
            sacc[nt][2] = __expf(sacc[nt][2] - mn1);
            sacc[nt][3] = __expf(sacc[nt][3] - mn1);
            rs0 += sacc[nt][0] + sacc[nt][1];
            rs1 += sacc[nt][2] + sacc[nt][3];
        }
#pragma unroll
        for (int off = 1; off <= 2; off <<= 1) {
            rs0 += __shfl_xor_sync(0xffffffffu, rs0, off);
            rs1 += __shfl_xor_sync(0xffffffffu, rs1, off);
        }
        l0 = l0 * alpha0 + rs0;
        l1 = l1 * alpha1 + rs1;
        m0 = mn0;
        m1 = mn1;
#pragma unroll
        for (int nt = 0; nt < 8; nt++) {
            oacc[nt][0] *= alpha0;
            oacc[nt][1] *= alpha0;
            oacc[nt][2] *= alpha1;
            oacc[nt][3] *= alpha1;
        }

        // P (C-frag) -> A-frag via intra-quad shuffles, then O += P.V
        const int srcA = (lane & ~3) | (c >> 1);
        const int srcB = srcA + 2;
#pragma unroll
        for (int kt = 0; kt < 8; kt++) {
            const float v00 = __shfl_sync(0xffffffffu, sacc[kt][0], srcA);
            const float v01 = __shfl_sync(0xffffffffu, sacc[kt][1], srcA);
            const float v20 = __shfl_sync(0xffffffffu, sacc[kt][2], srcA);
            const float v21 = __shfl_sync(0xffffffffu, sacc[kt][3], srcA);
            const float w00 = __shfl_sync(0xffffffffu, sacc[kt][0], srcB);
            const float w01 = __shfl_sync(0xffffffffu, sacc[kt][1], srcB);
            const float w20 = __shfl_sync(0xffffffffu, sacc[kt][2], srcB);
            const float w21 = __shfl_sync(0xffffffffu, sacc[kt][3], srcB);
            uint32_t af[4];
            af[0] = f2tf32((c & 1) ? v01 : v00);
            af[1] = f2tf32((c & 1) ? v21 : v20);
            af[2] = f2tf32((c & 1) ? w01 : w00);
            af[3] = f2tf32((c & 1) ? w21 : w20);
#pragma unroll
            for (int nt = 0; nt < 8; nt++) {
                uint32_t bf[2];
                const float* vp = Vs + (kt * 8 + c) * KVPITCH + nt * 8 + r;
                bf[0] = __float_as_uint(vp[0]);
                bf[1] = __float_as_uint(vp[4 * KVPITCH]);
                mma_tf32(oacc[nt], af, bf);
            }
        }
    }

    // epilogue: divide by l, round to tf32 (consumed by final GEMM), store
    const float inv0 = 1.0f / l0;
    const float inv1 = 1.0f / l1;
    float* Ob = O + ((size_t)(b * S + q0 + wrow) * D) + h * HD;
#pragma unroll
    for (int nt = 0; nt < 8; nt++) {
        const int col = nt * 8 + 2 * c;
        *reinterpret_cast<float2*>(Ob + (size_t)r * D + col) =
            make_float2(__uint_as_float(f2tf32(oacc[nt][0] * inv0)),
                        __uint_as_float(f2tf32(oacc[nt][1] * inv0)));
        *reinterpret_cast<float2*>(Ob + (size_t)(r + 8) * D + col) =
            make_float2(__uint_as_float(f2tf32(oacc[nt][2] * inv1)),
                        __uint_as_float(f2tf32(oacc[nt][3] * inv1)));
    }
}

// ---------------- launch ----------------
extern "C" void kernel_launch(void* const* d_in, const int* in_sizes, int n_in,
                              void* d_out, int out_size) {
    const float* x  = (const float*)d_in[0];
    const float* wq = (const float*)d_in[1];
    const float* wk = (const float*)d_in[2];
    const float* wv = (const float*)d_in[3];
    const float* wo = (const float*)d_in[4];
    float* out = (float*)d_out;

    float* q;   cudaGetSymbolAddress((void**)&q,   g_q);
    float* k;   cudaGetSymbolAddress((void**)&k,   g_k);
    float* v;   cudaGetSymbolAddress((void**)&v,   g_v);
    float* ao;  cudaGetSymbolAddress((void**)&ao,  g_ao);
    float* xr;  cudaGetSymbolAddress((void**)&xr,  g_x);
    float* wqr; cudaGetSymbolAddress((void**)&wqr, g_wq);
    float* wkr; cudaGetSymbolAddress((void**)&wkr, g_wk);
    float* wvr; cudaGetSymbolAddress((void**)&wvr, g_wv);
    float* wor; cudaGetSymbolAddress((void**)&wor, g_wo);

    cudaFuncSetAttribute(gemm_tc_kernel<true>,
                         cudaFuncAttributeMaxDynamicSharedMemorySize, GEMM_SMEM);
    cudaFuncSetAttribute(gemm_tc_kernel<false>,
                         cudaFuncAttributeMaxDynamicSharedMemorySize, GEMM_SMEM);
    cudaFuncSetAttribute(attn_tc_kernel,
                         cudaFuncAttributeMaxDynamicSharedMemorySize, ATTN_SMEM);

    // prep: round x + weights to tf32 once
    const int nx4 = MROWS * D / 4;         // 2097152
    const int nw4 = D * D / 4;             // 262144
    round_tf32_kernel<<<(nx4 + 255) / 256, 256>>>(x, xr, nx4);
    round_tf32_kernel<<<(nw4 + 255) / 256, 256>>>(wq, wqr, nw4);
    round_tf32_kernel<<<(nw4 + 255) / 256, 256>>>(wk, wkr, nw4);
    round_tf32_kernel<<<(nw4 + 255) / 256, 256>>>(wv, wvr, nw4);
    round_tf32_kernel<<<(nw4 + 255) / 256, 256>>>(wo, wor, nw4);

    dim3 gemm_grid(D / 128, MROWS / 128);   // (8, 64)
    gemm_tc_kernel<true><<<gemm_grid, 256, GEMM_SMEM>>>(xr, wqr, q);
    gemm_tc_kernel<true><<<gemm_grid, 256, GEMM_SMEM>>>(xr, wkr, k);
    gemm_tc_kernel<true><<<gemm_grid, 256, GEMM_SMEM>>>(xr, wvr, v);

    dim3 attn_grid(S / 64, H, B);           // (16, 16, 8)
    attn_tc_kernel<<<attn_grid, 128, ATTN_SMEM>>>(q, k, v, ao);

    gemm_tc_kernel<false><<<gemm_grid, 256, GEMM_SMEM>>>(ao, wor, out);
}